// round 10
// baseline (speedup 1.0000x reference)
#include <cuda_runtime.h>
#include <cstdint>

// ---------------------------------------------------------------------------
// DNPU layer: 128 per-node MLPs (7->90->90->90->90->1), B=16384.
// fp32 via packed fma.rn.f32x2 (FFMA2), weights staged in SMEM per node,
// activations ping-pong in SMEM, persistent grid-stride over work units.
// ---------------------------------------------------------------------------

#define HD        90      // hidden width
#define NNODE     128
#define BATCH     16384
#define NCOL      96      // padded column count (90 -> 96)
#define RS        132     // activation row stride in floats (128 rows + 4 pad)
#define TILE_ROWS 128
#define TILES_PER_UNIT 4
#define UNIT_ROWS (TILE_ROWS * TILES_PER_UNIT)     // 512
#define UNITS_PER_NODE (BATCH / UNIT_ROWS)         // 32
#define NUNITS (NNODE * UNITS_PER_NODE)            // 4096
#define NTHREADS 256

typedef unsigned long long u64;

// packed f32x2 FMA: d.lo = a.lo*b.lo + c.lo ; d.hi = a.hi*b.hi + c.hi
#define FMA2(d, a, b, c) \
    asm("fma.rn.f32x2 %0, %1, %2, %3;" : "=l"(d) : "l"(a), "l"(b), "l"(c))

// duplicate one float into both lanes of an f32x2
#define PACK_DUP(d, f) \
    asm("mov.b64 %0, {%1, %1};" : "=l"(d) : "r"(__float_as_uint(f)))

#define UNPACK2(lo, hi, v) \
    asm("mov.b64 {%0, %1}, %2;" : "=r"(lo), "=r"(hi) : "l"(v))

// One 128x96 output tile of  O = relu(A^T W + bias).
// A: [K][RS] col-major activations (row index contiguous)
// W: [K][NCOL] row-major weights
// O: [NCOL][RS]
// thread (tx,ty) owns rows ty*8..ty*8+7 and cols tx*6..tx*6+5.
template <int K, bool RELU>
__device__ __forceinline__ void gemm_tile(
    const float* __restrict__ A,
    const float* __restrict__ W,
    const float* __restrict__ bias,
    float* __restrict__ O,
    int tx, int ty)
{
    u64 acc[4][6];
#pragma unroll
    for (int c = 0; c < 6; c++) {
        float bv = bias[tx * 6 + c];
        u64 bb; PACK_DUP(bb, bv);
#pragma unroll
        for (int p = 0; p < 4; p++) acc[p][c] = bb;
    }

    const float* Ap = A + ty * 8;
    const float* Wp = W + tx * 6;

#pragma unroll 6
    for (int k = 0; k < K; k++) {
        // 8 activation rows = 4 packed row-pairs (broadcast across tx)
        ulonglong2 la0 = *(const ulonglong2*)(Ap + k * RS);
        ulonglong2 la1 = *(const ulonglong2*)(Ap + k * RS + 4);
        u64 av[4] = { la0.x, la0.y, la1.x, la1.y };

        // 6 weights for this k-row
        float2 w01 = *(const float2*)(Wp + k * NCOL);
        float2 w23 = *(const float2*)(Wp + k * NCOL + 2);
        float2 w45 = *(const float2*)(Wp + k * NCOL + 4);
        float wv[6] = { w01.x, w01.y, w23.x, w23.y, w45.x, w45.y };
        u64 bv2[6];
#pragma unroll
        for (int c = 0; c < 6; c++) PACK_DUP(bv2[c], wv[c]);

#pragma unroll
        for (int p = 0; p < 4; p++)
#pragma unroll
            for (int c = 0; c < 6; c++)
                FMA2(acc[p][c], av[p], bv2[c], acc[p][c]);
    }

    // epilogue: unpack, relu, store 2x float4 per column
#pragma unroll
    for (int c = 0; c < 6; c++) {
        int col = tx * 6 + c;
        float* op = O + col * RS + ty * 8;
        float v[8];
#pragma unroll
        for (int p = 0; p < 4; p++) {
            unsigned lo, hi;
            UNPACK2(lo, hi, acc[p][c]);
            float f0 = __uint_as_float(lo);
            float f1 = __uint_as_float(hi);
            if (RELU) { f0 = fmaxf(f0, 0.0f); f1 = fmaxf(f1, 0.0f); }
            v[2 * p]     = f0;
            v[2 * p + 1] = f1;
        }
        *(float4*)(op)     = make_float4(v[0], v[1], v[2], v[3]);
        *(float4*)(op + 4) = make_float4(v[4], v[5], v[6], v[7]);
    }
}

extern __shared__ float sm[];

__global__ void __launch_bounds__(NTHREADS, 1)
dnpu_kernel(const float* __restrict__ x,        // [B, N*3]
            const float* __restrict__ controls, // [N, 4]
            const float* __restrict__ W_in,     // [N, 7, 90]
            const float* __restrict__ b_in,     // [N, 90]
            const float* __restrict__ W_hid,    // [3, N, 90, 90]
            const float* __restrict__ b_hid,    // [3, N, 90]
            const float* __restrict__ W_out,    // [N, 90]
            const float* __restrict__ b_out,    // [N]
            float* __restrict__ out)            // [B, N]
{
    // SMEM layout
    float* bufA  = sm;                         // NCOL*RS
    float* bufB  = bufA + NCOL * RS;           // NCOL*RS
    float* Whs   = bufB + NCOL * RS;           // 3 * HD * NCOL
    float* Wins  = Whs + 3 * HD * NCOL;        // 3 * NCOL  (data-electrode rows)
    float* bias0 = Wins + 3 * NCOL;            // NCOL
    float* bhs   = bias0 + NCOL;               // 3 * NCOL
    float* Wouts = bhs + 3 * NCOL;             // NCOL

    const int tid = threadIdx.x;
    const int tx = tid & 15;
    const int ty = tid >> 4;

    // zero padded weight/bias columns once (pads are never re-written, never
    // read as outputs; zeroing keeps pad accumulators finite)
    for (int i = tid; i < 3 * HD; i += NTHREADS) {
#pragma unroll
        for (int c = HD; c < NCOL; c++) Whs[i * NCOL + c] = 0.0f;
    }
    if (tid < NCOL - HD) {
        int c = HD + tid;
        for (int r = 0; r < 3; r++) { Wins[r * NCOL + c] = 0.0f; bhs[r * NCOL + c] = 0.0f; }
        bias0[c] = 0.0f;
        Wouts[c] = 0.0f;
    }

    int prev_node = -1;
    for (int u = blockIdx.x; u < NUNITS; u += gridDim.x) {
        const int node  = u >> 5;          // UNITS_PER_NODE = 32
        const int chunk = u & 31;
        const int row0u = chunk * UNIT_ROWS;

        if (node != prev_node) {
            __syncthreads();   // previous unit's reads of weights done
            // stage hidden weights [3][90][90] -> [3][90][96]
            for (int l = 0; l < 3; l++) {
                const float* src = W_hid + (size_t)(l * NNODE + node) * (HD * HD);
                for (int idx = tid; idx < HD * HD; idx += NTHREADS) {
                    int k = idx / HD, c = idx - k * HD;
                    Whs[(l * HD + k) * NCOL + c] = src[idx];
                }
            }
            // input weights (data electrodes, rows 0..2)
            {
                const float* src = W_in + (size_t)node * 7 * HD;
                for (int idx = tid; idx < 3 * HD; idx += NTHREADS) {
                    int k = idx / HD, c = idx - k * HD;
                    Wins[k * NCOL + c] = src[idx];
                }
            }
            // fold control electrodes + b_in into bias0
            if (tid < HD) {
                const float* wi = W_in + ((size_t)node * 7 + 3) * HD + tid;
                float c0 = controls[node * 4 + 0];
                float c1 = controls[node * 4 + 1];
                float c2 = controls[node * 4 + 2];
                float c3 = controls[node * 4 + 3];
                float b = b_in[(size_t)node * HD + tid];
                b = fmaf(c0, wi[0 * HD], b);
                b = fmaf(c1, wi[1 * HD], b);
                b = fmaf(c2, wi[2 * HD], b);
                b = fmaf(c3, wi[3 * HD], b);
                bias0[tid] = b;
            }
            // hidden biases
            for (int idx = tid; idx < 3 * HD; idx += NTHREADS) {
                int l = idx / HD, c = idx - l * HD;
                bhs[l * NCOL + c] = b_hid[(size_t)(l * NNODE + node) * HD + c];
            }
            if (tid < HD) Wouts[tid] = W_out[(size_t)node * HD + tid];
            prev_node = node;
            __syncthreads();
        }
        const float bo = b_out[node];

        for (int t = 0; t < TILES_PER_UNIT; t++) {
            const int row0 = row0u + t * TILE_ROWS;

            // load x slice -> bufA cols 0..2 (col-major)
            if (tid < TILE_ROWS) {
                const float* xr = x + (size_t)(row0 + tid) * (NNODE * 3) + node * 3;
                bufA[0 * RS + tid] = xr[0];
                bufA[1 * RS + tid] = xr[1];
                bufA[2 * RS + tid] = xr[2];
            }
            __syncthreads();

            gemm_tile<3,  true>(bufA, Wins,              bias0,          bufB, tx, ty);
            __syncthreads();
            gemm_tile<HD, true>(bufB, Whs + 0 * HD * NCOL, bhs + 0 * NCOL, bufA, tx, ty);
            __syncthreads();
            gemm_tile<HD, true>(bufA, Whs + 1 * HD * NCOL, bhs + 1 * NCOL, bufB, tx, ty);
            __syncthreads();
            gemm_tile<HD, true>(bufB, Whs + 2 * HD * NCOL, bhs + 2 * NCOL, bufA, tx, ty);
            __syncthreads();

            // output layer: out[row, node] = dot(h, W_out) + b_out
            if (tid < TILE_ROWS) {
                float acc = bo;
#pragma unroll 10
                for (int c = 0; c < HD; c++)
                    acc = fmaf(bufA[c * RS + tid], Wouts[c], acc);
                out[(size_t)(row0 + tid) * NNODE + node] = acc;
            }
            __syncthreads();  // also protects bufA/weights for next unit
        }
    }
}

// SMEM bytes: (2*NCOL*RS + 3*HD*NCOL + 3*NCOL + NCOL + 3*NCOL + NCOL) * 4
static const int SMEM_BYTES =
    (2 * NCOL * RS + 3 * HD * NCOL + 8 * NCOL) * (int)sizeof(float);  // 208128

extern "C" void kernel_launch(void* const* d_in, const int* in_sizes, int n_in,
                              void* d_out, int out_size)
{
    (void)in_sizes; (void)n_in; (void)out_size;
    const float* x        = (const float*)d_in[0];
    const float* controls = (const float*)d_in[1];
    const float* W_in     = (const float*)d_in[2];
    const float* b_in     = (const float*)d_in[3];
    const float* W_hid    = (const float*)d_in[4];
    const float* b_hid    = (const float*)d_in[5];
    const float* W_out    = (const float*)d_in[6];
    const float* b_out    = (const float*)d_in[7];
    float* out = (float*)d_out;

    cudaFuncSetAttribute(dnpu_kernel,
                         cudaFuncAttributeMaxDynamicSharedMemorySize, SMEM_BYTES);

    int dev = 0, nsm = 148;
    cudaGetDevice(&dev);
    cudaDeviceGetAttribute(&nsm, cudaDevAttrMultiProcessorCount, dev);
    if (nsm < 1) nsm = 148;
    int grid = nsm;
    if (grid > NUNITS) grid = NUNITS;

    dnpu_kernel<<<grid, NTHREADS, SMEM_BYTES>>>(
        x, controls, W_in, b_in, W_hid, b_hid, W_out, b_out, out);
}

// round 11
// speedup vs baseline: 1.3731x; 1.3731x over previous
#include <cuda_runtime.h>
#include <cstdint>

// ---------------------------------------------------------------------------
// DNPU layer: 128 per-node MLPs (7->90->90->90->90->1), B=16384.
// fp32 via packed fma.rn.f32x2 (FFMA2), weights staged in SMEM per node,
// activations ping-pong in SMEM, persistent grid-stride over work units.
// ---------------------------------------------------------------------------

#define HD        90      // hidden width
#define NNODE     128
#define BATCH     16384
#define NCOL      96      // padded column count (90 -> 96)
#define RS        132     // activation row stride in floats (128 rows + 4 pad)
#define TILE_ROWS 128
#define TILES_PER_UNIT 4
#define UNIT_ROWS (TILE_ROWS * TILES_PER_UNIT)     // 512
#define UNITS_PER_NODE (BATCH / UNIT_ROWS)         // 32
#define NUNITS (NNODE * UNITS_PER_NODE)            // 4096
#define NTHREADS 256

typedef unsigned long long u64;

// packed f32x2 FMA: d.lo = a.lo*b.lo + c.lo ; d.hi = a.hi*b.hi + c.hi
#define FMA2(d, a, b, c) \
    asm("fma.rn.f32x2 %0, %1, %2, %3;" : "=l"(d) : "l"(a), "l"(b), "l"(c))

// duplicate one float into both lanes of an f32x2
#define PACK_DUP(d, f) \
    asm("mov.b64 %0, {%1, %1};" : "=l"(d) : "r"(__float_as_uint(f)))

#define UNPACK2(lo, hi, v) \
    asm("mov.b64 {%0, %1}, %2;" : "=r"(lo), "=r"(hi) : "l"(v))

// One 128x96 output tile of  O = relu(A^T W + bias).
// A: [K][RS] col-major activations (row index contiguous)
// W: [K][NCOL] row-major weights
// O: [NCOL][RS]
// thread (tx,ty) owns rows ty*8..ty*8+7 and cols tx*6..tx*6+5.
template <int K, bool RELU>
__device__ __forceinline__ void gemm_tile(
    const float* __restrict__ A,
    const float* __restrict__ W,
    const float* __restrict__ bias,
    float* __restrict__ O,
    int tx, int ty)
{
    u64 acc[4][6];
#pragma unroll
    for (int c = 0; c < 6; c++) {
        float bv = bias[tx * 6 + c];
        u64 bb; PACK_DUP(bb, bv);
#pragma unroll
        for (int p = 0; p < 4; p++) acc[p][c] = bb;
    }

    const float* Ap = A + ty * 8;
    const float* Wp = W + tx * 6;

#pragma unroll 6
    for (int k = 0; k < K; k++) {
        // 8 activation rows = 4 packed row-pairs (broadcast across tx)
        ulonglong2 la0 = *(const ulonglong2*)(Ap + k * RS);
        ulonglong2 la1 = *(const ulonglong2*)(Ap + k * RS + 4);
        u64 av[4] = { la0.x, la0.y, la1.x, la1.y };

        // 6 weights for this k-row
        float2 w01 = *(const float2*)(Wp + k * NCOL);
        float2 w23 = *(const float2*)(Wp + k * NCOL + 2);
        float2 w45 = *(const float2*)(Wp + k * NCOL + 4);
        float wv[6] = { w01.x, w01.y, w23.x, w23.y, w45.x, w45.y };
        u64 bv2[6];
#pragma unroll
        for (int c = 0; c < 6; c++) PACK_DUP(bv2[c], wv[c]);

#pragma unroll
        for (int p = 0; p < 4; p++)
#pragma unroll
            for (int c = 0; c < 6; c++)
                FMA2(acc[p][c], av[p], bv2[c], acc[p][c]);
    }

    // epilogue: unpack, relu, store 2x float4 per column
#pragma unroll
    for (int c = 0; c < 6; c++) {
        int col = tx * 6 + c;
        float* op = O + col * RS + ty * 8;
        float v[8];
#pragma unroll
        for (int p = 0; p < 4; p++) {
            unsigned lo, hi;
            UNPACK2(lo, hi, acc[p][c]);
            float f0 = __uint_as_float(lo);
            float f1 = __uint_as_float(hi);
            if (RELU) { f0 = fmaxf(f0, 0.0f); f1 = fmaxf(f1, 0.0f); }
            v[2 * p]     = f0;
            v[2 * p + 1] = f1;
        }
        *(float4*)(op)     = make_float4(v[0], v[1], v[2], v[3]);
        *(float4*)(op + 4) = make_float4(v[4], v[5], v[6], v[7]);
    }
}

extern __shared__ float sm[];

__global__ void __launch_bounds__(NTHREADS, 1)
dnpu_kernel(const float* __restrict__ x,        // [B, N*3]
            const float* __restrict__ controls, // [N, 4]
            const float* __restrict__ W_in,     // [N, 7, 90]
            const float* __restrict__ b_in,     // [N, 90]
            const float* __restrict__ W_hid,    // [3, N, 90, 90]
            const float* __restrict__ b_hid,    // [3, N, 90]
            const float* __restrict__ W_out,    // [N, 90]
            const float* __restrict__ b_out,    // [N]
            float* __restrict__ out)            // [B, N]
{
    // SMEM layout
    float* bufA  = sm;                         // NCOL*RS
    float* bufB  = bufA + NCOL * RS;           // NCOL*RS
    float* Whs   = bufB + NCOL * RS;           // 3 * HD * NCOL
    float* Wins  = Whs + 3 * HD * NCOL;        // 3 * NCOL  (data-electrode rows)
    float* bias0 = Wins + 3 * NCOL;            // NCOL
    float* bhs   = bias0 + NCOL;               // 3 * NCOL
    float* Wouts = bhs + 3 * NCOL;             // NCOL

    const int tid = threadIdx.x;
    const int tx = tid & 15;
    const int ty = tid >> 4;

    // zero padded weight/bias columns once (pads are never re-written, never
    // read as outputs; zeroing keeps pad accumulators finite)
    for (int i = tid; i < 3 * HD; i += NTHREADS) {
#pragma unroll
        for (int c = HD; c < NCOL; c++) Whs[i * NCOL + c] = 0.0f;
    }
    if (tid < NCOL - HD) {
        int c = HD + tid;
        for (int r = 0; r < 3; r++) { Wins[r * NCOL + c] = 0.0f; bhs[r * NCOL + c] = 0.0f; }
        bias0[c] = 0.0f;
        Wouts[c] = 0.0f;
    }

    int prev_node = -1;
    for (int u = blockIdx.x; u < NUNITS; u += gridDim.x) {
        const int node  = u >> 5;          // UNITS_PER_NODE = 32
        const int chunk = u & 31;
        const int row0u = chunk * UNIT_ROWS;

        if (node != prev_node) {
            __syncthreads();   // previous unit's reads of weights done
            // stage hidden weights [3][90][90] -> [3][90][96]
            for (int l = 0; l < 3; l++) {
                const float* src = W_hid + (size_t)(l * NNODE + node) * (HD * HD);
                for (int idx = tid; idx < HD * HD; idx += NTHREADS) {
                    int k = idx / HD, c = idx - k * HD;
                    Whs[(l * HD + k) * NCOL + c] = src[idx];
                }
            }
            // input weights (data electrodes, rows 0..2)
            {
                const float* src = W_in + (size_t)node * 7 * HD;
                for (int idx = tid; idx < 3 * HD; idx += NTHREADS) {
                    int k = idx / HD, c = idx - k * HD;
                    Wins[k * NCOL + c] = src[idx];
                }
            }
            // fold control electrodes + b_in into bias0
            if (tid < HD) {
                const float* wi = W_in + ((size_t)node * 7 + 3) * HD + tid;
                float c0 = controls[node * 4 + 0];
                float c1 = controls[node * 4 + 1];
                float c2 = controls[node * 4 + 2];
                float c3 = controls[node * 4 + 3];
                float b = b_in[(size_t)node * HD + tid];
                b = fmaf(c0, wi[0 * HD], b);
                b = fmaf(c1, wi[1 * HD], b);
                b = fmaf(c2, wi[2 * HD], b);
                b = fmaf(c3, wi[3 * HD], b);
                bias0[tid] = b;
            }
            // hidden biases
            for (int idx = tid; idx < 3 * HD; idx += NTHREADS) {
                int l = idx / HD, c = idx - l * HD;
                bhs[l * NCOL + c] = b_hid[(size_t)(l * NNODE + node) * HD + c];
            }
            if (tid < HD) Wouts[tid] = W_out[(size_t)node * HD + tid];
            prev_node = node;
            __syncthreads();
        }
        const float bo = b_out[node];

        for (int t = 0; t < TILES_PER_UNIT; t++) {
            const int row0 = row0u + t * TILE_ROWS;

            // load x slice -> bufA cols 0..2 (col-major)
            if (tid < TILE_ROWS) {
                const float* xr = x + (size_t)(row0 + tid) * (NNODE * 3) + node * 3;
                bufA[0 * RS + tid] = xr[0];
                bufA[1 * RS + tid] = xr[1];
                bufA[2 * RS + tid] = xr[2];
            }
            __syncthreads();

            gemm_tile<3,  true>(bufA, Wins,              bias0,          bufB, tx, ty);
            __syncthreads();
            gemm_tile<HD, true>(bufB, Whs + 0 * HD * NCOL, bhs + 0 * NCOL, bufA, tx, ty);
            __syncthreads();
            gemm_tile<HD, true>(bufA, Whs + 1 * HD * NCOL, bhs + 1 * NCOL, bufB, tx, ty);
            __syncthreads();
            gemm_tile<HD, true>(bufB, Whs + 2 * HD * NCOL, bhs + 2 * NCOL, bufA, tx, ty);
            __syncthreads();

            // output layer: out[row, node] = dot(h, W_out) + b_out
            if (tid < TILE_ROWS) {
                float acc = bo;
#pragma unroll 10
                for (int c = 0; c < HD; c++)
                    acc = fmaf(bufA[c * RS + tid], Wouts[c], acc);
                out[(size_t)(row0 + tid) * NNODE + node] = acc;
            }
            __syncthreads();  // also protects bufA/weights for next unit
        }
    }
}

// SMEM bytes: (2*NCOL*RS + 3*HD*NCOL + 3*NCOL + NCOL + 3*NCOL + NCOL) * 4
static const int SMEM_BYTES =
    (2 * NCOL * RS + 3 * HD * NCOL + 8 * NCOL) * (int)sizeof(float);  // 208128

extern "C" void kernel_launch(void* const* d_in, const int* in_sizes, int n_in,
                              void* d_out, int out_size)
{
    (void)in_sizes; (void)n_in; (void)out_size;
    const float* x        = (const float*)d_in[0];
    const float* controls = (const float*)d_in[1];
    const float* W_in     = (const float*)d_in[2];
    const float* b_in     = (const float*)d_in[3];
    const float* W_hid    = (const float*)d_in[4];
    const float* b_hid    = (const float*)d_in[5];
    const float* W_out    = (const float*)d_in[6];
    const float* b_out    = (const float*)d_in[7];
    float* out = (float*)d_out;

    cudaFuncSetAttribute(dnpu_kernel,
                         cudaFuncAttributeMaxDynamicSharedMemorySize, SMEM_BYTES);

    int dev = 0, nsm = 148;
    cudaGetDevice(&dev);
    cudaDeviceGetAttribute(&nsm, cudaDevAttrMultiProcessorCount, dev);
    if (nsm < 1) nsm = 148;
    int grid = nsm;
    if (grid > NUNITS) grid = NUNITS;

    dnpu_kernel<<<grid, NTHREADS, SMEM_BYTES>>>(
        x, controls, W_in, b_in, W_hid, b_hid, W_out, b_out, out);
}